// round 2
// baseline (speedup 1.0000x reference)
#include <cuda_runtime.h>
#include <math.h>

#define M_TOT 8192
#define C_DIM 1024
#define S_LEN 2048
#define NB 4

// Static scratch (no allocations allowed)
__device__ float g_h0[M_TOT * C_DIM];
__device__ float g_pred[M_TOT * C_DIM];
__device__ float g_hA[M_TOT * C_DIM];
__device__ float g_hB[M_TOT * C_DIM];
__device__ float g_qkv[(long)M_TOT * 3 * C_DIM];
__device__ float g_scores[(long)NB * S_LEN * S_LEN];
__device__ float g_att[M_TOT * C_DIM];

__device__ __forceinline__ float gelu_f(float x) {
    return 0.5f * x * (1.0f + erff(x * 0.70710678118654752f));
}

// C[M,N] = epilogue( scale * A[M,K] @ op(B) )   op(B)=B^T (NT) if TRANSB else B (NN)
// 128x128 tile, BK=8, 256 threads, 8x8 microtile per thread.
template <bool TRANSB>
__global__ void __launch_bounds__(256, 2) gemm_kernel(
    const float* __restrict__ A, const float* __restrict__ B, float* __restrict__ C,
    int M, int N, int K, int lda, int ldb, int ldc,
    long sA, long sB, long sC,
    const float* __restrict__ bias, const float* __restrict__ residual,
    float scale, int act, int pe)
{
    __shared__ float As[8][128];
    __shared__ float Bs[8][128];
    long bz = blockIdx.z;
    A += bz * sA;
    B += bz * sB;
    C += bz * sC;
    const float* res = residual ? residual + bz * sC : nullptr;

    int row0 = blockIdx.y * 128, col0 = blockIdx.x * 128;
    int tid = threadIdx.x;
    int tx = tid & 15, ty = tid >> 4;
    int arow = tid >> 1;            // 0..127
    int acol = (tid & 1) << 2;      // 0 or 4

    float acc[8][8];
#pragma unroll
    for (int i = 0; i < 8; i++)
#pragma unroll
        for (int j = 0; j < 8; j++) acc[i][j] = 0.f;

    for (int k0 = 0; k0 < K; k0 += 8) {
        float4 av = *(const float4*)(A + (long)(row0 + arow) * lda + k0 + acol);
        As[acol + 0][arow] = av.x; As[acol + 1][arow] = av.y;
        As[acol + 2][arow] = av.z; As[acol + 3][arow] = av.w;
        if (TRANSB) {
            float4 bv = *(const float4*)(B + (long)(col0 + arow) * ldb + k0 + acol);
            Bs[acol + 0][arow] = bv.x; Bs[acol + 1][arow] = bv.y;
            Bs[acol + 2][arow] = bv.z; Bs[acol + 3][arow] = bv.w;
        } else {
            int bk = tid >> 5;            // 0..7
            int bn = (tid & 31) << 2;     // 0..124
            float4 bv = *(const float4*)(B + (long)(k0 + bk) * ldb + col0 + bn);
            *(float4*)(&Bs[bk][bn]) = bv;
        }
        __syncthreads();
#pragma unroll
        for (int k = 0; k < 8; k++) {
            float4 a0 = *(const float4*)(&As[k][ty * 8]);
            float4 a1 = *(const float4*)(&As[k][ty * 8 + 4]);
            float4 b0 = *(const float4*)(&Bs[k][tx * 8]);
            float4 b1 = *(const float4*)(&Bs[k][tx * 8 + 4]);
            float a[8] = {a0.x, a0.y, a0.z, a0.w, a1.x, a1.y, a1.z, a1.w};
            float b[8] = {b0.x, b0.y, b0.z, b0.w, b1.x, b1.y, b1.z, b1.w};
#pragma unroll
            for (int i = 0; i < 8; i++)
#pragma unroll
                for (int j = 0; j < 8; j++)
                    acc[i][j] = fmaf(a[i], b[j], acc[i][j]);
        }
        __syncthreads();
    }

#pragma unroll
    for (int i = 0; i < 8; i++) {
        int r = row0 + ty * 8 + i;
#pragma unroll
        for (int j = 0; j < 8; j++) {
            int c = col0 + tx * 8 + j;
            float v = acc[i][j] * scale;
            if (bias) v += bias[c];
            if (act) v = gelu_f(v);
            if (res) v += res[(long)r * ldc + c];
            if (pe) {
                int s = r & (S_LEN - 1);
                // div = 1000^(-2c/1024) = exp(-c * 2/1024 * ln(1000))
                float div = expf((float)c * (-2.0f / 1024.0f) * 6.9077552789821370521f);
                float ang = (float)s * div;
                v += (s & 1) ? cosf(ang) : sinf(ang);
            }
            C[(long)r * ldc + c] = v;
        }
    }
}

// In-place layernorm over last dim (1024). One block (256 thr) per row.
__global__ void layernorm_kernel(float* __restrict__ h,
                                 const float* __restrict__ g,
                                 const float* __restrict__ b)
{
    __shared__ float sa[8], sb[8];
    long row = blockIdx.x;
    float* p = h + row * C_DIM;
    int tid = threadIdx.x;
    float v[4];
    float s1 = 0.f, s2 = 0.f;
#pragma unroll
    for (int i = 0; i < 4; i++) {
        v[i] = p[tid + i * 256];
        s1 += v[i];
        s2 += v[i] * v[i];
    }
#pragma unroll
    for (int o = 16; o > 0; o >>= 1) {
        s1 += __shfl_down_sync(0xffffffffu, s1, o);
        s2 += __shfl_down_sync(0xffffffffu, s2, o);
    }
    int lane = tid & 31, w = tid >> 5;
    if (lane == 0) { sa[w] = s1; sb[w] = s2; }
    __syncthreads();
    if (tid < 32) {
        s1 = (tid < 8) ? sa[tid] : 0.f;
        s2 = (tid < 8) ? sb[tid] : 0.f;
#pragma unroll
        for (int o = 4; o > 0; o >>= 1) {
            s1 += __shfl_down_sync(0xffffffffu, s1, o);
            s2 += __shfl_down_sync(0xffffffffu, s2, o);
        }
        if (tid == 0) { sa[0] = s1; sb[0] = s2; }
    }
    __syncthreads();
    float mu = sa[0] * (1.0f / 1024.0f);
    float var = sb[0] * (1.0f / 1024.0f) - mu * mu;
    float inv = rsqrtf(var + 1e-5f);
#pragma unroll
    for (int i = 0; i < 4; i++) {
        int c = tid + i * 256;
        p[c] = (v[i] - mu) * inv * g[c] + b[c];
    }
}

// In-place softmax over last dim (1024). One block (256 thr) per row.
__global__ void softmax_kernel(float* __restrict__ att)
{
    __shared__ float sh[8];
    long row = blockIdx.x;
    float* p = att + row * C_DIM;
    int tid = threadIdx.x;
    float v[4];
    float m = -INFINITY;
#pragma unroll
    for (int i = 0; i < 4; i++) {
        v[i] = p[tid + i * 256];
        m = fmaxf(m, v[i]);
    }
#pragma unroll
    for (int o = 16; o > 0; o >>= 1)
        m = fmaxf(m, __shfl_down_sync(0xffffffffu, m, o));
    int lane = tid & 31, w = tid >> 5;
    if (lane == 0) sh[w] = m;
    __syncthreads();
    if (tid < 32) {
        m = (tid < 8) ? sh[tid] : -INFINITY;
#pragma unroll
        for (int o = 4; o > 0; o >>= 1)
            m = fmaxf(m, __shfl_down_sync(0xffffffffu, m, o));
        if (tid == 0) sh[0] = m;
    }
    __syncthreads();
    m = sh[0];
    __syncthreads();
    float e[4];
    float s = 0.f;
#pragma unroll
    for (int i = 0; i < 4; i++) {
        e[i] = expf(v[i] - m);
        s += e[i];
    }
#pragma unroll
    for (int o = 16; o > 0; o >>= 1)
        s += __shfl_down_sync(0xffffffffu, s, o);
    if (lane == 0) sh[w] = s;
    __syncthreads();
    if (tid < 32) {
        s = (tid < 8) ? sh[tid] : 0.f;
#pragma unroll
        for (int o = 4; o > 0; o >>= 1)
            s += __shfl_down_sync(0xffffffffu, s, o);
        if (tid == 0) sh[0] = s;
    }
    __syncthreads();
    float inv = 1.0f / sh[0];
#pragma unroll
    for (int i = 0; i < 4; i++)
        p[tid + i * 256] = e[i] * inv;
}

extern "C" void kernel_launch(void* const* d_in, const int* in_sizes, int n_in,
                              void* d_out, int out_size)
{
    const float* x        = (const float*)d_in[0];
    const float* fc_in_w  = (const float*)d_in[1];
    const float* fc_in_b  = (const float*)d_in[2];
    const float* ln_g     = (const float*)d_in[3];
    const float* ln_b     = (const float*)d_in[4];
    const float* qkv_w    = (const float*)d_in[5];
    const float* qkv_b    = (const float*)d_in[6];
    const float* proj_w   = (const float*)d_in[7];
    const float* proj_b   = (const float*)d_in[8];
    const float* fc_out_w = (const float*)d_in[9];
    const float* fc_out_b = (const float*)d_in[10];
    float* out = (float*)d_out;

    float *h0, *pred, *hA, *hB, *qkv, *scores, *att;
    cudaGetSymbolAddress((void**)&h0, g_h0);
    cudaGetSymbolAddress((void**)&pred, g_pred);
    cudaGetSymbolAddress((void**)&hA, g_hA);
    cudaGetSymbolAddress((void**)&hB, g_hB);
    cudaGetSymbolAddress((void**)&qkv, g_qkv);
    cudaGetSymbolAddress((void**)&scores, g_scores);
    cudaGetSymbolAddress((void**)&att, g_att);

    dim3 blk(256);

    // h = x @ fc_in_w^T + fc_in_b
    gemm_kernel<true><<<dim3(C_DIM / 128, M_TOT / 128, 1), blk>>>(
        x, fc_in_w, h0, M_TOT, C_DIM, C_DIM, C_DIM, C_DIM, C_DIM,
        0, 0, 0, fc_in_b, nullptr, 1.0f, 0, 0);

    // h = layer_norm(h)
    layernorm_kernel<<<M_TOT, 256>>>(h0, ln_g, ln_b);

    float* cur = h0;
    for (int i = 0; i < 4; i++) {
        float* outp = (i == 0) ? pred : (i == 1) ? hA : (i == 2) ? hB : hA;
        const float* resid = (i == 0) ? nullptr : pred;

        // qkv = gelu(h @ qkv_w[i]^T + qkv_b[i])   [8192, 3072]
        gemm_kernel<true><<<dim3(3 * C_DIM / 128, M_TOT / 128, 1), blk>>>(
            cur, qkv_w + (long)i * 3 * C_DIM * C_DIM, qkv,
            M_TOT, 3 * C_DIM, C_DIM, C_DIM, C_DIM, 3 * C_DIM,
            0, 0, 0, qkv_b + (long)i * 3 * C_DIM, nullptr, 1.0f, 1, 0);

        // scores[b] = q[b] @ k[b]^T / C   (batched NT, q/k strided inside qkv)
        gemm_kernel<true><<<dim3(S_LEN / 128, S_LEN / 128, NB), blk>>>(
            qkv, qkv + C_DIM, scores,
            S_LEN, S_LEN, C_DIM, 3 * C_DIM, 3 * C_DIM, S_LEN,
            (long)S_LEN * 3 * C_DIM, (long)S_LEN * 3 * C_DIM, (long)S_LEN * S_LEN,
            nullptr, nullptr, 1.0f / 1024.0f, 0, 0);

        // att[b] = scores[b] @ v[b]   (batched NN)
        gemm_kernel<false><<<dim3(C_DIM / 128, S_LEN / 128, NB), blk>>>(
            scores, qkv + 2 * C_DIM, att,
            S_LEN, C_DIM, S_LEN, S_LEN, 3 * C_DIM, C_DIM,
            (long)S_LEN * S_LEN, (long)S_LEN * 3 * C_DIM, (long)S_LEN * C_DIM,
            nullptr, nullptr, 1.0f, 0, 0);

        // att = softmax(att, axis=-1)
        softmax_kernel<<<M_TOT, 256>>>(att);

        // h = gelu(att @ proj_w[i]^T + proj_b[i]) (+ pred for i>0)
        gemm_kernel<true><<<dim3(C_DIM / 128, M_TOT / 128, 1), blk>>>(
            att, proj_w + (long)i * C_DIM * C_DIM, outp,
            M_TOT, C_DIM, C_DIM, C_DIM, C_DIM, C_DIM,
            0, 0, 0, proj_b + (long)i * C_DIM, resid, 1.0f, 1, 0);

        cur = outp;
    }

    // out = h @ fc_out_w^T + fc_out_b + pose_enc
    gemm_kernel<true><<<dim3(C_DIM / 128, M_TOT / 128, 1), blk>>>(
        cur, fc_out_w, out, M_TOT, C_DIM, C_DIM, C_DIM, C_DIM, C_DIM,
        0, 0, 0, fc_out_b, nullptr, 1.0f, 0, 1);
}

// round 4
// speedup vs baseline: 2.5565x; 2.5565x over previous
#include <cuda_runtime.h>
#include <cuda_bf16.h>
#include <math.h>
#include <stdint.h>

#define M_TOT 8192
#define C_DIM 1024
#define S_LEN 2048
#define NB 4

// ---------------- static scratch (no allocations allowed) ----------------
__device__ float g_h0[M_TOT * C_DIM];
__device__ float g_pred[M_TOT * C_DIM];
__device__ float g_hA[M_TOT * C_DIM];
__device__ float g_hB[M_TOT * C_DIM];
__device__ float g_qkv[(long)M_TOT * 3 * C_DIM];
__device__ float g_scores[(long)NB * S_LEN * S_LEN];
__device__ float g_att[M_TOT * C_DIM];
__device__ float g_vt[(long)NB * C_DIM * S_LEN];

// ---------------- helpers ----------------
__device__ __forceinline__ uint32_t smem_u32(const void* p) {
    uint32_t a;
    asm("{ .reg .u64 t; cvta.to.shared.u64 t, %1; cvt.u32.u64 %0, t; }" : "=r"(a) : "l"(p));
    return a;
}
__device__ __forceinline__ float gelu_f(float x) {
    return 0.5f * x * (1.0f + erff(x * 0.70710678118654752f));
}
__device__ __forceinline__ uint32_t bf2_bits(__nv_bfloat162 v) {
    return *reinterpret_cast<uint32_t*>(&v);
}
__device__ __forceinline__ void split4(float4 f, uint2& hi, uint2& lo) {
    __nv_bfloat162 h01 = __floats2bfloat162_rn(f.x, f.y);
    __nv_bfloat162 h23 = __floats2bfloat162_rn(f.z, f.w);
    float2 g01 = __bfloat1622float2(h01), g23 = __bfloat1622float2(h23);
    __nv_bfloat162 l01 = __floats2bfloat162_rn(f.x - g01.x, f.y - g01.y);
    __nv_bfloat162 l23 = __floats2bfloat162_rn(f.z - g23.x, f.w - g23.y);
    hi = make_uint2(bf2_bits(h01), bf2_bits(h23));
    lo = make_uint2(bf2_bits(l01), bf2_bits(l23));
}
__device__ __forceinline__ void ldsm4(uint32_t* r, uint32_t addr) {
    asm volatile("ldmatrix.sync.aligned.m8n8.x4.shared.b16 {%0,%1,%2,%3}, [%4];"
        : "=r"(r[0]), "=r"(r[1]), "=r"(r[2]), "=r"(r[3]) : "r"(addr));
}
__device__ __forceinline__ void ldsm2(uint32_t* r, uint32_t addr) {
    asm volatile("ldmatrix.sync.aligned.m8n8.x2.shared.b16 {%0,%1}, [%2];"
        : "=r"(r[0]), "=r"(r[1]) : "r"(addr));
}
__device__ __forceinline__ void mma16816(float* d, const uint32_t* a, const uint32_t* b) {
    asm volatile("mma.sync.aligned.m16n8k16.row.col.f32.bf16.bf16.f32 "
        "{%0,%1,%2,%3}, {%4,%5,%6,%7}, {%8,%9}, {%0,%1,%2,%3};"
        : "+f"(d[0]), "+f"(d[1]), "+f"(d[2]), "+f"(d[3])
        : "r"(a[0]), "r"(a[1]), "r"(a[2]), "r"(a[3]), "r"(b[0]), "r"(b[1]));
}

// SMEM: 4 tiles of 128 rows x 32 bf16, row stride 80B (ldmatrix conflict-free)
#define ROW_B 80
#define OFF_AH 0
#define OFF_AL 10240
#define OFF_BH 20480
#define OFF_BL 30720
#define SM_TOT 40960

// D[M,N] = epi(scale * A[M,K] @ B[N,K]^T)  (NT), bf16x3 split on warp-MMA (HMMA).
// CTA tile 128x128, BK=32, 256 threads = 8 warps (2 M x 4 N), warp tile 64x32.
__global__ void __launch_bounds__(256) gemm_bf16x3(
    const float* __restrict__ A, const float* __restrict__ B, float* __restrict__ C,
    int K, int lda, int ldb, int ldc,
    long sA, long sB, long sC,
    const float* __restrict__ bias, const float* __restrict__ residual,
    float scale, int act, int pe)
{
    __shared__ char sm[SM_TOT];
    uint32_t sb = smem_u32(sm);

    int tid = threadIdx.x, wid = tid >> 5, lane = tid & 31;
    long bz = blockIdx.z;
    A += bz * sA; B += bz * sB; C += bz * sC;
    const float* res = residual ? residual + bz * sC : nullptr;
    long row0 = (long)blockIdx.y * 128, col0 = (long)blockIdx.x * 128;

    int wm = wid >> 2, wn = wid & 3;         // 2 x 4 warp grid
    int m0w = wm * 64, n0w = wn * 32;

    float acc[4][4][4];
#pragma unroll
    for (int i = 0; i < 4; i++)
#pragma unroll
        for (int j = 0; j < 4; j++)
#pragma unroll
            for (int e = 0; e < 4; e++) acc[i][j][e] = 0.f;

    // per-thread load map: quad q = j*256+tid -> row q>>3 (0..127), kq q&7 (4 floats)
    const int r_ld = tid >> 3;               // base row for j=0 (tid/8)
    const int kq_ld = tid & 7;
    const int NC = K >> 5;

    // ldmatrix addresses (fixed per thread, + ks*32 bytes per k16 step)
    uint32_t a_addr_h[4], a_addr_l[4], b_addr_h[4], b_addr_l[4];
#pragma unroll
    for (int i = 0; i < 4; i++) {
        uint32_t r = m0w + i * 16 + (lane & 15);
        uint32_t byt = r * ROW_B + (lane >> 4) * 16;
        a_addr_h[i] = sb + OFF_AH + byt;
        a_addr_l[i] = sb + OFF_AL + byt;
    }
#pragma unroll
    for (int j = 0; j < 4; j++) {
        uint32_t r = n0w + j * 8 + (lane & 7);
        uint32_t byt = r * ROW_B + ((lane >> 3) & 1) * 16;
        b_addr_h[j] = sb + OFF_BH + byt;
        b_addr_l[j] = sb + OFF_BL + byt;
    }

    float4 pa[4], pb[4];
#pragma unroll
    for (int j = 0; j < 4; j++) {
        int r = r_ld + j * 32;
        pa[j] = *(const float4*)(A + (row0 + r) * lda + kq_ld * 4);
        pb[j] = *(const float4*)(B + (col0 + r) * ldb + kq_ld * 4);
    }

    for (int c = 0; c < NC; c++) {
        // convert + STS (hi/lo split)
#pragma unroll
        for (int j = 0; j < 4; j++) {
            int r = r_ld + j * 32;
            uint32_t off = (uint32_t)(r * ROW_B + kq_ld * 8);
            uint2 hi, lo;
            split4(pa[j], hi, lo);
            *(uint2*)(sm + OFF_AH + off) = hi;
            *(uint2*)(sm + OFF_AL + off) = lo;
            split4(pb[j], hi, lo);
            *(uint2*)(sm + OFF_BH + off) = hi;
            *(uint2*)(sm + OFF_BL + off) = lo;
        }
        __syncthreads();

        // prefetch next chunk while MMAing this one
        if (c + 1 < NC) {
            long k0 = (long)(c + 1) * 32;
#pragma unroll
            for (int j = 0; j < 4; j++) {
                int r = r_ld + j * 32;
                pa[j] = *(const float4*)(A + (row0 + r) * lda + k0 + kq_ld * 4);
                pb[j] = *(const float4*)(B + (col0 + r) * ldb + k0 + kq_ld * 4);
            }
        }

#pragma unroll
        for (int ks = 0; ks < 2; ks++) {
            uint32_t ah[4][4], al[4][4], bh[4][2], bl[4][2];
#pragma unroll
            for (int i = 0; i < 4; i++) {
                ldsm4(ah[i], a_addr_h[i] + ks * 32);
                ldsm4(al[i], a_addr_l[i] + ks * 32);
            }
#pragma unroll
            for (int j = 0; j < 4; j++) {
                ldsm2(bh[j], b_addr_h[j] + ks * 32);
                ldsm2(bl[j], b_addr_l[j] + ks * 32);
            }
#pragma unroll
            for (int i = 0; i < 4; i++)
#pragma unroll
                for (int j = 0; j < 4; j++) mma16816(acc[i][j], ah[i], bh[j]);
#pragma unroll
            for (int i = 0; i < 4; i++)
#pragma unroll
                for (int j = 0; j < 4; j++) mma16816(acc[i][j], ah[i], bl[j]);
#pragma unroll
            for (int i = 0; i < 4; i++)
#pragma unroll
                for (int j = 0; j < 4; j++) mma16816(acc[i][j], al[i], bh[j]);
        }
        __syncthreads();
    }

    // epilogue: thread holds C[r1][cc..cc+1], C[r1+8][cc..cc+1] per (i,j)
#pragma unroll
    for (int i = 0; i < 4; i++) {
        long r1 = row0 + m0w + i * 16 + (lane >> 2);
        long r2 = r1 + 8;
#pragma unroll
        for (int j = 0; j < 4; j++) {
            long cc = col0 + n0w + j * 8 + 2 * (lane & 3);
            float2 bi = bias ? *(const float2*)(bias + cc) : make_float2(0.f, 0.f);
            float v0 = acc[i][j][0] * scale + bi.x;
            float v1 = acc[i][j][1] * scale + bi.y;
            float v2 = acc[i][j][2] * scale + bi.x;
            float v3 = acc[i][j][3] * scale + bi.y;
            if (act) { v0 = gelu_f(v0); v1 = gelu_f(v1); v2 = gelu_f(v2); v3 = gelu_f(v3); }
            if (res) {
                float2 q1 = *(const float2*)(res + r1 * ldc + cc);
                float2 q2 = *(const float2*)(res + r2 * ldc + cc);
                v0 += q1.x; v1 += q1.y; v2 += q2.x; v3 += q2.y;
            }
            if (pe) {
                float d0 = expf((float)cc * (-2.0f / 1024.0f) * 6.9077552789821370521f);
                float d1 = expf((float)(cc + 1) * (-2.0f / 1024.0f) * 6.9077552789821370521f);
                int s1 = (int)(r1 & (S_LEN - 1)), s2 = (int)(r2 & (S_LEN - 1));
                float a10 = s1 * d0, a11 = s1 * d1, a20 = s2 * d0, a21 = s2 * d1;
                v0 += (s1 & 1) ? cosf(a10) : sinf(a10);
                v1 += (s1 & 1) ? cosf(a11) : sinf(a11);
                v2 += (s2 & 1) ? cosf(a20) : sinf(a20);
                v3 += (s2 & 1) ? cosf(a21) : sinf(a21);
            }
            *(float2*)(C + r1 * ldc + cc) = make_float2(v0, v1);
            *(float2*)(C + r2 * ldc + cc) = make_float2(v2, v3);
        }
    }
}

// v^T per batch: vt[b][c][s] = qkv[b*S + s][2C + c]
__global__ void transpose_v(const float* __restrict__ qkv, float* __restrict__ vt)
{
    __shared__ float t[32][33];
    int b = blockIdx.z;
    int s0 = blockIdx.x * 32, c0 = blockIdx.y * 32;
    int tx = threadIdx.x, ty = threadIdx.y;
    const float* src = qkv + (long)b * S_LEN * 3 * C_DIM + 2 * C_DIM;
#pragma unroll
    for (int i = 0; i < 32; i += 8)
        t[ty + i][tx] = src[(long)(s0 + ty + i) * (3 * C_DIM) + c0 + tx];
    __syncthreads();
    float* dst = vt + (long)b * C_DIM * S_LEN;
#pragma unroll
    for (int i = 0; i < 32; i += 8)
        dst[(long)(c0 + ty + i) * S_LEN + s0 + tx] = t[tx][ty + i];
}

// In-place layernorm over last dim (1024). One block (256 thr) per row.
__global__ void layernorm_kernel(float* __restrict__ h,
                                 const float* __restrict__ g,
                                 const float* __restrict__ b)
{
    __shared__ float sa[8], sb[8];
    long row = blockIdx.x;
    float* p = h + row * C_DIM;
    int tid = threadIdx.x;
    float v[4];
    float s1 = 0.f, s2 = 0.f;
#pragma unroll
    for (int i = 0; i < 4; i++) {
        v[i] = p[tid + i * 256];
        s1 += v[i];
        s2 += v[i] * v[i];
    }
#pragma unroll
    for (int o = 16; o > 0; o >>= 1) {
        s1 += __shfl_down_sync(0xffffffffu, s1, o);
        s2 += __shfl_down_sync(0xffffffffu, s2, o);
    }
    int lane = tid & 31, w = tid >> 5;
    if (lane == 0) { sa[w] = s1; sb[w] = s2; }
    __syncthreads();
    if (tid < 32) {
        s1 = (tid < 8) ? sa[tid] : 0.f;
        s2 = (tid < 8) ? sb[tid] : 0.f;
#pragma unroll
        for (int o = 4; o > 0; o >>= 1) {
            s1 += __shfl_down_sync(0xffffffffu, s1, o);
            s2 += __shfl_down_sync(0xffffffffu, s2, o);
        }
        if (tid == 0) { sa[0] = s1; sb[0] = s2; }
    }
    __syncthreads();
    float mu = sa[0] * (1.0f / 1024.0f);
    float var = sb[0] * (1.0f / 1024.0f) - mu * mu;
    float inv = rsqrtf(var + 1e-5f);
#pragma unroll
    for (int i = 0; i < 4; i++) {
        int c = tid + i * 256;
        p[c] = (v[i] - mu) * inv * g[c] + b[c];
    }
}

// In-place softmax over last dim (1024). One block (256 thr) per row.
__global__ void softmax_kernel(float* __restrict__ att)
{
    __shared__ float sh[8];
    long row = blockIdx.x;
    float* p = att + row * C_DIM;
    int tid = threadIdx.x;
    float v[4];
    float m = -INFINITY;
#pragma unroll
    for (int i = 0; i < 4; i++) {
        v[i] = p[tid + i * 256];
        m = fmaxf(m, v[i]);
    }
#pragma unroll
    for (int o = 16; o > 0; o >>= 1)
        m = fmaxf(m, __shfl_down_sync(0xffffffffu, m, o));
    int lane = tid & 31, w = tid >> 5;
    if (lane == 0) sh[w] = m;
    __syncthreads();
    if (tid < 32) {
        m = (tid < 8) ? sh[tid] : -INFINITY;
#pragma unroll
        for (int o = 4; o > 0; o >>= 1)
            m = fmaxf(m, __shfl_down_sync(0xffffffffu, m, o));
        if (tid == 0) sh[0] = m;
    }
    __syncthreads();
    m = sh[0];
    __syncthreads();
    float e[4];
    float s = 0.f;
#pragma unroll
    for (int i = 0; i < 4; i++) {
        e[i] = expf(v[i] - m);
        s += e[i];
    }
#pragma unroll
    for (int o = 16; o > 0; o >>= 1)
        s += __shfl_down_sync(0xffffffffu, s, o);
    if (lane == 0) sh[w] = s;
    __syncthreads();
    if (tid < 32) {
        s = (tid < 8) ? sh[tid] : 0.f;
#pragma unroll
        for (int o = 4; o > 0; o >>= 1)
            s += __shfl_down_sync(0xffffffffu, s, o);
        if (tid == 0) sh[0] = s;
    }
    __syncthreads();
    float inv = 1.0f / sh[0];
#pragma unroll
    for (int i = 0; i < 4; i++)
        p[tid + i * 256] = e[i] * inv;
}

static void launch_gemm(const float* A, const float* B, float* C,
                        int M, int N, int K, int lda, int ldb, int ldc,
                        long sA, long sB, long sC, int batches,
                        const float* bias, const float* residual,
                        float scale, int act, int pe)
{
    dim3 grid(N / 128, M / 128, batches);
    gemm_bf16x3<<<grid, 256>>>(A, B, C, K, lda, ldb, ldc,
                               sA, sB, sC, bias, residual, scale, act, pe);
}

extern "C" void kernel_launch(void* const* d_in, const int* in_sizes, int n_in,
                              void* d_out, int out_size)
{
    const float* x        = (const float*)d_in[0];
    const float* fc_in_w  = (const float*)d_in[1];
    const float* fc_in_b  = (const float*)d_in[2];
    const float* ln_g     = (const float*)d_in[3];
    const float* ln_b     = (const float*)d_in[4];
    const float* qkv_w    = (const float*)d_in[5];
    const float* qkv_b    = (const float*)d_in[6];
    const float* proj_w   = (const float*)d_in[7];
    const float* proj_b   = (const float*)d_in[8];
    const float* fc_out_w = (const float*)d_in[9];
    const float* fc_out_b = (const float*)d_in[10];
    float* out = (float*)d_out;

    float *h0, *pred, *hA, *hB, *qkv, *scores, *att, *vt;
    cudaGetSymbolAddress((void**)&h0, g_h0);
    cudaGetSymbolAddress((void**)&pred, g_pred);
    cudaGetSymbolAddress((void**)&hA, g_hA);
    cudaGetSymbolAddress((void**)&hB, g_hB);
    cudaGetSymbolAddress((void**)&qkv, g_qkv);
    cudaGetSymbolAddress((void**)&scores, g_scores);
    cudaGetSymbolAddress((void**)&att, g_att);
    cudaGetSymbolAddress((void**)&vt, g_vt);

    // h = x @ fc_in_w^T + fc_in_b
    launch_gemm(x, fc_in_w, h0, M_TOT, C_DIM, C_DIM, C_DIM, C_DIM, C_DIM,
                0, 0, 0, 1, fc_in_b, nullptr, 1.0f, 0, 0);

    layernorm_kernel<<<M_TOT, 256>>>(h0, ln_g, ln_b);

    float* cur = h0;
    for (int i = 0; i < 4; i++) {
        float* outp = (i == 0) ? pred : (i == 1) ? hA : (i == 2) ? hB : hA;
        const float* resid = (i == 0) ? nullptr : pred;

        // qkv = gelu(h @ qkv_w[i]^T + qkv_b[i])
        launch_gemm(cur, qkv_w + (long)i * 3 * C_DIM * C_DIM, qkv,
                    M_TOT, 3 * C_DIM, C_DIM, C_DIM, C_DIM, 3 * C_DIM,
                    0, 0, 0, 1, qkv_b + (long)i * 3 * C_DIM, nullptr, 1.0f, 1, 0);

        // vt[b] = v[b]^T
        transpose_v<<<dim3(S_LEN / 32, C_DIM / 32, NB), dim3(32, 8)>>>(qkv, vt);

        // scores[b] = q[b] @ k[b]^T / C
        launch_gemm(qkv, qkv + C_DIM, scores,
                    S_LEN, S_LEN, C_DIM, 3 * C_DIM, 3 * C_DIM, S_LEN,
                    (long)S_LEN * 3 * C_DIM, (long)S_LEN * 3 * C_DIM, (long)S_LEN * S_LEN,
                    NB, nullptr, nullptr, 1.0f / 1024.0f, 0, 0);

        // att[b] = scores[b] @ vt[b]^T   (NT with vt = v^T)
        launch_gemm(scores, vt, att,
                    S_LEN, C_DIM, S_LEN, S_LEN, S_LEN, C_DIM,
                    (long)S_LEN * S_LEN, (long)C_DIM * S_LEN, (long)S_LEN * C_DIM,
                    NB, nullptr, nullptr, 1.0f, 0, 0);

        softmax_kernel<<<M_TOT, 256>>>(att);

        // h = gelu(att @ proj_w[i]^T + proj_b[i]) (+ pred for i>0)
        launch_gemm(att, proj_w + (long)i * C_DIM * C_DIM, outp,
                    M_TOT, C_DIM, C_DIM, C_DIM, C_DIM, C_DIM,
                    0, 0, 0, 1, proj_b + (long)i * C_DIM, resid, 1.0f, 1, 0);

        cur = outp;
    }

    // out = h @ fc_out_w^T + fc_out_b + pose_enc
    launch_gemm(cur, fc_out_w, out, M_TOT, C_DIM, C_DIM, C_DIM, C_DIM, C_DIM,
                0, 0, 0, 1, fc_out_b, nullptr, 1.0f, 0, 1);
}

// round 5
// speedup vs baseline: 2.6620x; 1.0413x over previous
#include <cuda_runtime.h>
#include <cuda_bf16.h>
#include <math.h>
#include <stdint.h>

#define M_TOT 8192
#define C_DIM 1024
#define S_LEN 2048
#define NB 4

// ---------------- static scratch (no allocations allowed) ----------------
// fp32
__device__ float g_h0[M_TOT * C_DIM];
__device__ float g_att[M_TOT * C_DIM];
__device__ float g_pred[M_TOT * C_DIM];
// bf16 hi/lo split buffers
#define W_FCIN 0
#define W_QKV  1048576
#define W_PROJ 13631488
#define W_FCOUT 17825792
#define W_TOTAL 18874368
__device__ __nv_bfloat16 g_w_hi[W_TOTAL];
__device__ __nv_bfloat16 g_w_lo[W_TOTAL];
__device__ __nv_bfloat16 g_x_hi[M_TOT * C_DIM];
__device__ __nv_bfloat16 g_x_lo[M_TOT * C_DIM];
__device__ __nv_bfloat16 g_a_hi[M_TOT * C_DIM];
__device__ __nv_bfloat16 g_a_lo[M_TOT * C_DIM];
__device__ __nv_bfloat16 g_qkv_hi[(long)M_TOT * 3 * C_DIM];
__device__ __nv_bfloat16 g_qkv_lo[(long)M_TOT * 3 * C_DIM];
__device__ __nv_bfloat16 g_vt_hi[(long)NB * C_DIM * S_LEN];
__device__ __nv_bfloat16 g_vt_lo[(long)NB * C_DIM * S_LEN];
__device__ __nv_bfloat16 g_sc_hi[(long)NB * S_LEN * S_LEN];
__device__ __nv_bfloat16 g_sc_lo[(long)NB * S_LEN * S_LEN];
__device__ __nv_bfloat16 g_sm_hi[M_TOT * C_DIM];
__device__ __nv_bfloat16 g_sm_lo[M_TOT * C_DIM];

// ---------------- helpers ----------------
__device__ __forceinline__ uint32_t smem_u32(const void* p) {
    uint32_t a;
    asm("{ .reg .u64 t; cvta.to.shared.u64 t, %1; cvt.u32.u64 %0, t; }" : "=r"(a) : "l"(p));
    return a;
}
__device__ __forceinline__ float gelu_f(float x) {
    return 0.5f * x * (1.0f + erff(x * 0.70710678118654752f));
}
__device__ __forceinline__ uint32_t bf2_bits(__nv_bfloat162 v) {
    return *reinterpret_cast<uint32_t*>(&v);
}
__device__ __forceinline__ void split4(float4 f, uint2& hi, uint2& lo) {
    __nv_bfloat162 h01 = __floats2bfloat162_rn(f.x, f.y);
    __nv_bfloat162 h23 = __floats2bfloat162_rn(f.z, f.w);
    float2 g01 = __bfloat1622float2(h01), g23 = __bfloat1622float2(h23);
    __nv_bfloat162 l01 = __floats2bfloat162_rn(f.x - g01.x, f.y - g01.y);
    __nv_bfloat162 l23 = __floats2bfloat162_rn(f.z - g23.x, f.w - g23.y);
    hi = make_uint2(bf2_bits(h01), bf2_bits(h23));
    lo = make_uint2(bf2_bits(l01), bf2_bits(l23));
}
__device__ __forceinline__ void split2(float a, float b, uint32_t& hi, uint32_t& lo) {
    __nv_bfloat162 h = __floats2bfloat162_rn(a, b);
    float2 g = __bfloat1622float2(h);
    __nv_bfloat162 l = __floats2bfloat162_rn(a - g.x, b - g.y);
    hi = bf2_bits(h); lo = bf2_bits(l);
}
__device__ __forceinline__ void ldsm4(uint32_t* r, uint32_t addr) {
    asm volatile("ldmatrix.sync.aligned.m8n8.x4.shared.b16 {%0,%1,%2,%3}, [%4];"
        : "=r"(r[0]), "=r"(r[1]), "=r"(r[2]), "=r"(r[3]) : "r"(addr));
}
__device__ __forceinline__ void ldsm2(uint32_t* r, uint32_t addr) {
    asm volatile("ldmatrix.sync.aligned.m8n8.x2.shared.b16 {%0,%1}, [%2];"
        : "=r"(r[0]), "=r"(r[1]) : "r"(addr));
}
__device__ __forceinline__ void mma16816(float* d, const uint32_t* a, const uint32_t* b) {
    asm volatile("mma.sync.aligned.m16n8k16.row.col.f32.bf16.bf16.f32 "
        "{%0,%1,%2,%3}, {%4,%5,%6,%7}, {%8,%9}, {%0,%1,%2,%3};"
        : "+f"(d[0]), "+f"(d[1]), "+f"(d[2]), "+f"(d[3])
        : "r"(a[0]), "r"(a[1]), "r"(a[2]), "r"(a[3]), "r"(b[0]), "r"(b[1]));
}
#define CP16(dst, src) \
    asm volatile("cp.async.ca.shared.global [%0], [%1], 16;" :: "r"(dst), "l"(src) : "memory")
#define CP_COMMIT() asm volatile("cp.async.commit_group;" ::: "memory")
#define CP_WAIT1() asm volatile("cp.async.wait_group 1;" ::: "memory")

// SMEM stage layout: 4 tiles (AH, AL, BH, BL) of 128 rows x 32 bf16, row stride 80B
#define ROW_B 80
#define TILE_B 10240
#define STAGE_B 40960
#define SM_TOT (2 * STAGE_B)

// D[M,N] = epi(scale * A[M,K] @ B[N,K]^T), pre-split bf16 inputs, HMMA, 2-stage cp.async.
// CTA tile 128x128, BK=32, 256 threads = 8 warps (2 M x 4 N), warp tile 64x32.
__global__ void __launch_bounds__(256) gemm_sp(
    const __nv_bfloat16* __restrict__ Ahi, const __nv_bfloat16* __restrict__ Alo,
    const __nv_bfloat16* __restrict__ Bhi, const __nv_bfloat16* __restrict__ Blo,
    float* __restrict__ C, __nv_bfloat16* __restrict__ Ohi, __nv_bfloat16* __restrict__ Olo,
    int K, int lda, int ldb, int ldc,
    long sA, long sB, long sC,
    const float* __restrict__ bias, const float* __restrict__ residual,
    float scale, int act, int pe)
{
    extern __shared__ char sm[];
    uint32_t sb = smem_u32(sm);

    int tid = threadIdx.x, wid = tid >> 5, lane = tid & 31;
    long bz = blockIdx.z;
    Ahi += bz * sA; Alo += bz * sA; Bhi += bz * sB; Blo += bz * sB;
    if (C) C += bz * sC;
    if (Ohi) { Ohi += bz * sC; Olo += bz * sC; }
    const float* res = residual ? residual + bz * sC : nullptr;
    long row0 = (long)blockIdx.y * 128, col0 = (long)blockIdx.x * 128;

    int wm = wid >> 2, wn = wid & 3;
    int m0w = wm * 64, n0w = wn * 32;

    float acc[4][4][4];
#pragma unroll
    for (int i = 0; i < 4; i++)
#pragma unroll
        for (int j = 0; j < 4; j++)
#pragma unroll
            for (int e = 0; e < 4; e++) acc[i][j][e] = 0.f;

    // loader map: row = tid>>1 (0..127), segs 2*(tid&1), 2*(tid&1)+1 (16B each)
    const int r_ld = tid >> 1;
    const int sg = (tid & 1) * 2;
    const int NC = K >> 5;

    const __nv_bfloat16* a_hi_src = Ahi + (row0 + r_ld) * lda + sg * 8;
    const __nv_bfloat16* a_lo_src = Alo + (row0 + r_ld) * lda + sg * 8;
    const __nv_bfloat16* b_hi_src = Bhi + (col0 + r_ld) * ldb + sg * 8;
    const __nv_bfloat16* b_lo_src = Blo + (col0 + r_ld) * ldb + sg * 8;
    uint32_t st_base = sb + r_ld * ROW_B + sg * 16;

    auto issue = [&](int c, int buf) {
        long ko = (long)c * 32;
        uint32_t d = st_base + buf * STAGE_B;
        CP16(d,              a_hi_src + ko);
        CP16(d + 16,         a_hi_src + ko + 8);
        CP16(d + TILE_B,     a_lo_src + ko);
        CP16(d + TILE_B + 16, a_lo_src + ko + 8);
        CP16(d + 2 * TILE_B,      b_hi_src + ko);
        CP16(d + 2 * TILE_B + 16, b_hi_src + ko + 8);
        CP16(d + 3 * TILE_B,      b_lo_src + ko);
        CP16(d + 3 * TILE_B + 16, b_lo_src + ko + 8);
    };

    // ldmatrix addresses (stage 0 base; add buf*STAGE_B)
    uint32_t a_addr_h[4], a_addr_l[4], b_addr_h[4], b_addr_l[4];
#pragma unroll
    for (int i = 0; i < 4; i++) {
        uint32_t r = m0w + i * 16 + (lane & 15);
        uint32_t byt = r * ROW_B + (lane >> 4) * 16;
        a_addr_h[i] = sb + byt;
        a_addr_l[i] = sb + TILE_B + byt;
    }
#pragma unroll
    for (int j = 0; j < 4; j++) {
        uint32_t r = n0w + j * 8 + (lane & 7);
        uint32_t byt = r * ROW_B + ((lane >> 3) & 1) * 16;
        b_addr_h[j] = sb + 2 * TILE_B + byt;
        b_addr_l[j] = sb + 3 * TILE_B + byt;
    }

    issue(0, 0); CP_COMMIT();
    if (NC > 1) issue(1, 1);
    CP_COMMIT();

    for (int c = 0; c < NC; c++) {
        CP_WAIT1();
        __syncthreads();
        uint32_t bofs = (c & 1) * STAGE_B;
#pragma unroll
        for (int ks = 0; ks < 2; ks++) {
            uint32_t ah[4][4], al[4][4], bh[4][2], bl[4][2];
#pragma unroll
            for (int i = 0; i < 4; i++) {
                ldsm4(ah[i], a_addr_h[i] + bofs + ks * 32);
                ldsm4(al[i], a_addr_l[i] + bofs + ks * 32);
            }
#pragma unroll
            for (int j = 0; j < 4; j++) {
                ldsm2(bh[j], b_addr_h[j] + bofs + ks * 32);
                ldsm2(bl[j], b_addr_l[j] + bofs + ks * 32);
            }
#pragma unroll
            for (int i = 0; i < 4; i++)
#pragma unroll
                for (int j = 0; j < 4; j++) mma16816(acc[i][j], ah[i], bh[j]);
#pragma unroll
            for (int i = 0; i < 4; i++)
#pragma unroll
                for (int j = 0; j < 4; j++) mma16816(acc[i][j], ah[i], bl[j]);
#pragma unroll
            for (int i = 0; i < 4; i++)
#pragma unroll
                for (int j = 0; j < 4; j++) mma16816(acc[i][j], al[i], bh[j]);
        }
        __syncthreads();
        if (c + 2 < NC) issue(c + 2, c & 1);
        CP_COMMIT();
    }

    // epilogue: thread holds C[r1][cc..cc+1], C[r1+8][cc..cc+1] per (i,j)
#pragma unroll
    for (int i = 0; i < 4; i++) {
        long r1 = row0 + m0w + i * 16 + (lane >> 2);
        long r2 = r1 + 8;
#pragma unroll
        for (int j = 0; j < 4; j++) {
            long cc = col0 + n0w + j * 8 + 2 * (lane & 3);
            float2 bi = bias ? *(const float2*)(bias + cc) : make_float2(0.f, 0.f);
            float v0 = acc[i][j][0] * scale + bi.x;
            float v1 = acc[i][j][1] * scale + bi.y;
            float v2 = acc[i][j][2] * scale + bi.x;
            float v3 = acc[i][j][3] * scale + bi.y;
            if (act) { v0 = gelu_f(v0); v1 = gelu_f(v1); v2 = gelu_f(v2); v3 = gelu_f(v3); }
            if (res) {
                float2 q1 = *(const float2*)(res + r1 * ldc + cc);
                float2 q2 = *(const float2*)(res + r2 * ldc + cc);
                v0 += q1.x; v1 += q1.y; v2 += q2.x; v3 += q2.y;
            }
            if (pe) {
                float d0 = expf((float)cc * (-2.0f / 1024.0f) * 6.9077552789821370521f);
                float d1 = expf((float)(cc + 1) * (-2.0f / 1024.0f) * 6.9077552789821370521f);
                int s1 = (int)(r1 & (S_LEN - 1)), s2 = (int)(r2 & (S_LEN - 1));
                float a10 = s1 * d0, a11 = s1 * d1, a20 = s2 * d0, a21 = s2 * d1;
                v0 += (s1 & 1) ? cosf(a10) : sinf(a10);
                v1 += (s1 & 1) ? cosf(a11) : sinf(a11);
                v2 += (s2 & 1) ? cosf(a20) : sinf(a20);
                v3 += (s2 & 1) ? cosf(a21) : sinf(a21);
            }
            if (C) {
                *(float2*)(C + r1 * ldc + cc) = make_float2(v0, v1);
                *(float2*)(C + r2 * ldc + cc) = make_float2(v2, v3);
            }
            if (Ohi) {
                uint32_t h, l;
                split2(v0, v1, h, l);
                *(uint32_t*)(Ohi + r1 * ldc + cc) = h;
                *(uint32_t*)(Olo + r1 * ldc + cc) = l;
                split2(v2, v3, h, l);
                *(uint32_t*)(Ohi + r2 * ldc + cc) = h;
                *(uint32_t*)(Olo + r2 * ldc + cc) = l;
            }
        }
    }
}

// fp32 -> bf16 hi/lo split, grid-stride over float4s
__global__ void split_kernel(const float* __restrict__ src,
                             __nv_bfloat16* __restrict__ hi,
                             __nv_bfloat16* __restrict__ lo, long n4)
{
    long i = (long)blockIdx.x * blockDim.x + threadIdx.x;
    long stride = (long)gridDim.x * blockDim.x;
    for (; i < n4; i += stride) {
        float4 f = ((const float4*)src)[i];
        uint2 h, l;
        split4(f, h, l);
        ((uint2*)hi)[i] = h;
        ((uint2*)lo)[i] = l;
    }
}

// vt[b][c][s] = qkv[b,s,2C+c], split form
__global__ void transpose_v_bf(const __nv_bfloat16* __restrict__ qh,
                               const __nv_bfloat16* __restrict__ ql,
                               __nv_bfloat16* __restrict__ vh,
                               __nv_bfloat16* __restrict__ vl)
{
    __shared__ __nv_bfloat16 th[32][34], tl[32][34];
    int b = blockIdx.z;
    int s0 = blockIdx.x * 32, c0 = blockIdx.y * 32;
    int tx = threadIdx.x, ty = threadIdx.y;
    const __nv_bfloat16* sh = qh + (long)b * S_LEN * 3 * C_DIM + 2 * C_DIM;
    const __nv_bfloat16* sl = ql + (long)b * S_LEN * 3 * C_DIM + 2 * C_DIM;
#pragma unroll
    for (int i = 0; i < 32; i += 8) {
        long o = (long)(s0 + ty + i) * (3 * C_DIM) + c0 + tx;
        th[ty + i][tx] = sh[o];
        tl[ty + i][tx] = sl[o];
    }
    __syncthreads();
    __nv_bfloat16* dh = vh + (long)b * C_DIM * S_LEN;
    __nv_bfloat16* dl = vl + (long)b * C_DIM * S_LEN;
#pragma unroll
    for (int i = 0; i < 32; i += 8) {
        long o = (long)(c0 + ty + i) * S_LEN + s0 + tx;
        dh[o] = th[tx][ty + i];
        dl[o] = tl[tx][ty + i];
    }
}

// layernorm over last dim (1024), fp32 in -> split bf16 out
__global__ void layernorm_kernel(const float* __restrict__ h,
                                 const float* __restrict__ g,
                                 const float* __restrict__ b,
                                 __nv_bfloat16* __restrict__ ohi,
                                 __nv_bfloat16* __restrict__ olo)
{
    __shared__ float sa[8], sb2[8];
    long row = blockIdx.x;
    const float* p = h + row * C_DIM;
    int tid = threadIdx.x;
    float v[4];
    float s1 = 0.f, s2 = 0.f;
#pragma unroll
    for (int i = 0; i < 4; i++) {
        v[i] = p[tid + i * 256];
        s1 += v[i];
        s2 += v[i] * v[i];
    }
#pragma unroll
    for (int o = 16; o > 0; o >>= 1) {
        s1 += __shfl_down_sync(0xffffffffu, s1, o);
        s2 += __shfl_down_sync(0xffffffffu, s2, o);
    }
    int lane = tid & 31, w = tid >> 5;
    if (lane == 0) { sa[w] = s1; sb2[w] = s2; }
    __syncthreads();
    if (tid < 32) {
        s1 = (tid < 8) ? sa[tid] : 0.f;
        s2 = (tid < 8) ? sb2[tid] : 0.f;
#pragma unroll
        for (int o = 4; o > 0; o >>= 1) {
            s1 += __shfl_down_sync(0xffffffffu, s1, o);
            s2 += __shfl_down_sync(0xffffffffu, s2, o);
        }
        if (tid == 0) { sa[0] = s1; sb2[0] = s2; }
    }
    __syncthreads();
    float mu = sa[0] * (1.0f / 1024.0f);
    float var = sb2[0] * (1.0f / 1024.0f) - mu * mu;
    float inv = rsqrtf(var + 1e-5f);
#pragma unroll
    for (int i = 0; i < 4; i++) {
        int c = tid + i * 256;
        float y = (v[i] - mu) * inv * g[c] + b[c];
        __nv_bfloat16 hb = __float2bfloat16_rn(y);
        ohi[row * C_DIM + c] = hb;
        olo[row * C_DIM + c] = __float2bfloat16_rn(y - __bfloat162float(hb));
    }
}

// softmax over last dim (1024), fp32 in -> split bf16 out
__global__ void softmax_kernel(const float* __restrict__ att,
                               __nv_bfloat16* __restrict__ ohi,
                               __nv_bfloat16* __restrict__ olo)
{
    __shared__ float sh[8];
    long row = blockIdx.x;
    const float* p = att + row * C_DIM;
    int tid = threadIdx.x;
    float v[4];
    float m = -INFINITY;
#pragma unroll
    for (int i = 0; i < 4; i++) {
        v[i] = p[tid + i * 256];
        m = fmaxf(m, v[i]);
    }
#pragma unroll
    for (int o = 16; o > 0; o >>= 1)
        m = fmaxf(m, __shfl_down_sync(0xffffffffu, m, o));
    int lane = tid & 31, w = tid >> 5;
    if (lane == 0) sh[w] = m;
    __syncthreads();
    if (tid < 32) {
        m = (tid < 8) ? sh[tid] : -INFINITY;
#pragma unroll
        for (int o = 4; o > 0; o >>= 1)
            m = fmaxf(m, __shfl_down_sync(0xffffffffu, m, o));
        if (tid == 0) sh[0] = m;
    }
    __syncthreads();
    m = sh[0];
    __syncthreads();
    float e[4];
    float s = 0.f;
#pragma unroll
    for (int i = 0; i < 4; i++) {
        e[i] = expf(v[i] - m);
        s += e[i];
    }
#pragma unroll
    for (int o = 16; o > 0; o >>= 1)
        s += __shfl_down_sync(0xffffffffu, s, o);
    if (lane == 0) sh[w] = s;
    __syncthreads();
    if (tid < 32) {
        s = (tid < 8) ? sh[tid] : 0.f;
#pragma unroll
        for (int o = 4; o > 0; o >>= 1)
            s += __shfl_down_sync(0xffffffffu, s, o);
        if (tid == 0) sh[0] = s;
    }
    __syncthreads();
    float inv = 1.0f / sh[0];
#pragma unroll
    for (int i = 0; i < 4; i++) {
        int c = tid + i * 256;
        float y = e[i] * inv;
        __nv_bfloat16 hb = __float2bfloat16_rn(y);
        ohi[row * C_DIM + c] = hb;
        olo[row * C_DIM + c] = __float2bfloat16_rn(y - __bfloat162float(hb));
    }
}

struct Bufs {
    __nv_bfloat16 *whi, *wlo, *xhi, *xlo, *ahi, *alo, *qhi, *qlo, *vhi, *vlo, *schi, *sclo, *smhi, *smlo;
    float *h0, *att, *pred;
};

static void launch_gemm(const __nv_bfloat16* Ahi, const __nv_bfloat16* Alo,
                        const __nv_bfloat16* Bhi, const __nv_bfloat16* Blo,
                        float* C, __nv_bfloat16* Ohi, __nv_bfloat16* Olo,
                        int M, int N, int K, int lda, int ldb, int ldc,
                        long sA, long sB, long sC, int batches,
                        const float* bias, const float* residual,
                        float scale, int act, int pe)
{
    dim3 grid(N / 128, M / 128, batches);
    gemm_sp<<<grid, 256, SM_TOT>>>(Ahi, Alo, Bhi, Blo, C, Ohi, Olo, K, lda, ldb, ldc,
                                   sA, sB, sC, bias, residual, scale, act, pe);
}

extern "C" void kernel_launch(void* const* d_in, const int* in_sizes, int n_in,
                              void* d_out, int out_size)
{
    const float* x        = (const float*)d_in[0];
    const float* fc_in_w  = (const float*)d_in[1];
    const float* fc_in_b  = (const float*)d_in[2];
    const float* ln_g     = (const float*)d_in[3];
    const float* ln_b     = (const float*)d_in[4];
    const float* qkv_w    = (const float*)d_in[5];
    const float* qkv_b    = (const float*)d_in[6];
    const float* proj_w   = (const float*)d_in[7];
    const float* proj_b   = (const float*)d_in[8];
    const float* fc_out_w = (const float*)d_in[9];
    const float* fc_out_b = (const float*)d_in[10];
    float* out = (float*)d_out;

    static bool attr_set = false;
    if (!attr_set) {
        cudaFuncSetAttribute(gemm_sp, cudaFuncAttributeMaxDynamicSharedMemorySize, SM_TOT);
        attr_set = true;
    }

    Bufs b;
    cudaGetSymbolAddress((void**)&b.whi, g_w_hi);
    cudaGetSymbolAddress((void**)&b.wlo, g_w_lo);
    cudaGetSymbolAddress((void**)&b.xhi, g_x_hi);
    cudaGetSymbolAddress((void**)&b.xlo, g_x_lo);
    cudaGetSymbolAddress((void**)&b.ahi, g_a_hi);
    cudaGetSymbolAddress((void**)&b.alo, g_a_lo);
    cudaGetSymbolAddress((void**)&b.qhi, g_qkv_hi);
    cudaGetSymbolAddress((void**)&b.qlo, g_qkv_lo);
    cudaGetSymbolAddress((void**)&b.vhi, g_vt_hi);
    cudaGetSymbolAddress((void**)&b.vlo, g_vt_lo);
    cudaGetSymbolAddress((void**)&b.schi, g_sc_hi);
    cudaGetSymbolAddress((void**)&b.sclo, g_sc_lo);
    cudaGetSymbolAddress((void**)&b.smhi, g_sm_hi);
    cudaGetSymbolAddress((void**)&b.smlo, g_sm_lo);
    cudaGetSymbolAddress((void**)&b.h0, g_h0);
    cudaGetSymbolAddress((void**)&b.att, g_att);
    cudaGetSymbolAddress((void**)&b.pred, g_pred);

    // split inputs/weights
    split_kernel<<<512, 256>>>(x, b.xhi, b.xlo, (long)M_TOT * C_DIM / 4);
    split_kernel<<<256, 256>>>(fc_in_w, b.whi + W_FCIN, b.wlo + W_FCIN, (long)C_DIM * C_DIM / 4);
    split_kernel<<<1024, 256>>>(qkv_w, b.whi + W_QKV, b.wlo + W_QKV, (long)4 * 3 * C_DIM * C_DIM / 4);
    split_kernel<<<512, 256>>>(proj_w, b.whi + W_PROJ, b.wlo + W_PROJ, (long)4 * C_DIM * C_DIM / 4);
    split_kernel<<<256, 256>>>(fc_out_w, b.whi + W_FCOUT, b.wlo + W_FCOUT, (long)C_DIM * C_DIM / 4);

    // h0 = x @ fc_in_w^T + fc_in_b    (fp32 out only)
    launch_gemm(b.xhi, b.xlo, b.whi + W_FCIN, b.wlo + W_FCIN, b.h0, nullptr, nullptr,
                M_TOT, C_DIM, C_DIM, C_DIM, C_DIM, C_DIM, 0, 0, 0, 1,
                fc_in_b, nullptr, 1.0f, 0, 0);

    // a = split(layernorm(h0))
    layernorm_kernel<<<M_TOT, 256>>>(b.h0, ln_g, ln_b, b.ahi, b.alo);

    for (int i = 0; i < 4; i++) {
        long wq = W_QKV + (long)i * 3 * C_DIM * C_DIM;
        long wp = W_PROJ + (long)i * C_DIM * C_DIM;

        // qkv = split(gelu(a @ qkv_w[i]^T + qkv_b[i]))   (split out only)
        launch_gemm(b.ahi, b.alo, b.whi + wq, b.wlo + wq, nullptr, b.qhi, b.qlo,
                    M_TOT, 3 * C_DIM, C_DIM, C_DIM, C_DIM, 3 * C_DIM, 0, 0, 0, 1,
                    qkv_b + (long)i * 3 * C_DIM, nullptr, 1.0f, 1, 0);

        // vt = split transpose of v
        transpose_v_bf<<<dim3(S_LEN / 32, C_DIM / 32, NB), dim3(32, 8)>>>(b.qhi, b.qlo, b.vhi, b.vlo);

        // scores = split(q @ k^T / C)   (split out only, batched)
        launch_gemm(b.qhi, b.qlo, b.qhi + C_DIM, b.qlo + C_DIM, nullptr, b.schi, b.sclo,
                    S_LEN, S_LEN, C_DIM, 3 * C_DIM, 3 * C_DIM, S_LEN,
                    (long)S_LEN * 3 * C_DIM, (long)S_LEN * 3 * C_DIM, (long)S_LEN * S_LEN,
                    NB, nullptr, nullptr, 1.0f / 1024.0f, 0, 0);

        // att = scores @ vt^T   (fp32 out, batched)
        launch_gemm(b.schi, b.sclo, b.vhi, b.vlo, b.att, nullptr, nullptr,
                    S_LEN, C_DIM, S_LEN, S_LEN, S_LEN, C_DIM,
                    (long)S_LEN * S_LEN, (long)C_DIM * S_LEN, (long)S_LEN * C_DIM,
                    NB, nullptr, nullptr, 1.0f, 0, 0);

        // sm = split(softmax(att))
        softmax_kernel<<<M_TOT, 256>>>(b.att, b.smhi, b.smlo);

        // a = split(gelu(sm @ proj_w[i]^T + proj_b[i]) [+ pred]); fp32 pred copy on i==0
        launch_gemm(b.smhi, b.smlo, b.whi + wp, b.wlo + wp,
                    (i == 0) ? b.pred : nullptr, b.ahi, b.alo,
                    M_TOT, C_DIM, C_DIM, C_DIM, C_DIM, C_DIM, 0, 0, 0, 1,
                    proj_b + (long)i * C_DIM, (i == 0) ? nullptr : b.pred, 1.0f, 1, 0);
    }

    // out = a @ fc_out_w^T + fc_out_b + pose_enc
    launch_gemm(b.ahi, b.alo, b.whi + W_FCOUT, b.wlo + W_FCOUT, out, nullptr, nullptr,
                M_TOT, C_DIM, C_DIM, C_DIM, C_DIM, C_DIM, 0, 0, 0, 1,
                fc_out_b, nullptr, 1.0f, 0, 1);
}